// round 13
// baseline (speedup 1.0000x reference)
#include <cuda_runtime.h>
#include <math.h>

// Problem constants
#define Bn 8
#define Wn 32
#define Hn 32
#define Cn 64
#define NHn 8
#define POSn 1024          // W*H
#define OCn 512            // NH*C
#define CENTER 31

// Device scratch (allocation-free rule: static __device__ globals)
__device__ float g_Q[Bn * POSn * OCn];     // 16 MB
__device__ float g_K[Bn * POSn * OCn];     // 16 MB
__device__ float g_mix[Bn * POSn * OCn];   // 16 MB

// ---------------------------------------------------------------------------
// Kernel A: Q/K projections.  out[pos, o] = sum_c hs[pos,c]*W[o,c] + b[o]
// grid: (8192/64, 512/64, 2)   block: 256
// ---------------------------------------------------------------------------
__global__ __launch_bounds__(256)
void vox_proj_kernel(const float* __restrict__ hs,
                     const float* __restrict__ Wq, const float* __restrict__ bq,
                     const float* __restrict__ Wk, const float* __restrict__ bk)
{
    const float* Wm = blockIdx.z ? Wk : Wq;
    const float* bm = blockIdx.z ? bk : bq;
    float* outp = blockIdx.z ? g_K : g_Q;

    __shared__ float As[64 * 65];
    __shared__ float Ws[64 * 65];

    const int r0 = blockIdx.x * 64;
    const int c0 = blockIdx.y * 64;
    const int tid = threadIdx.x;

    for (int idx = tid; idx < 64 * 64; idx += 256) {
        int r = idx >> 6, c = idx & 63;
        As[r * 65 + c] = hs[(size_t)(r0 + r) * 64 + c];
        Ws[r * 65 + c] = Wm[(size_t)(c0 + r) * 64 + c];   // Ws[o_local][k]
    }
    __syncthreads();

    const int ty = tid >> 4;   // 0..15 -> 4 rows each
    const int tx = tid & 15;   // 0..15 -> 4 cols each

    float acc[4][4] = {};
#pragma unroll
    for (int k = 0; k < 64; k++) {
        float a[4], w[4];
#pragma unroll
        for (int u = 0; u < 4; u++) a[u] = As[(ty * 4 + u) * 65 + k];
#pragma unroll
        for (int v = 0; v < 4; v++) w[v] = Ws[(tx * 4 + v) * 65 + k];
#pragma unroll
        for (int u = 0; u < 4; u++)
#pragma unroll
            for (int v = 0; v < 4; v++)
                acc[u][v] += a[u] * w[v];
    }

#pragma unroll
    for (int u = 0; u < 4; u++) {
        float4 o;
        o.x = acc[u][0] + bm[c0 + tx * 4 + 0];
        o.y = acc[u][1] + bm[c0 + tx * 4 + 1];
        o.z = acc[u][2] + bm[c0 + tx * 4 + 2];
        o.w = acc[u][3] + bm[c0 + tx * 4 + 3];
        *reinterpret_cast<float4*>(&outp[(size_t)(r0 + ty * 4 + u) * OCn + c0 + tx * 4]) = o;
    }
}

// ---------------------------------------------------------------------------
// Kernel B: fused relative-bias attention (flash-style, online softmax).
// One block per (b, h, i) : 32 queries (j=0..31) x 1024 keys.
// grid: 2048   block: 256
// ---------------------------------------------------------------------------
__global__ __launch_bounds__(256)
void vox_attn_kernel(const float* __restrict__ hs,
                     const float* __restrict__ row_emb,
                     const float* __restrict__ col_emb)
{
    __shared__ __align__(16) float KH[64 * 33 + 32 * 64]; // Kst(2112f) + Hs(2048f); phase1: Remb+Cemb alias
    __shared__ float Qs[32 * 65];   // [q][d], pad 65
    __shared__ float RB[32 * 33];   // rb[q][k]
    __shared__ float CB[32 * 33];   // cb[q][l]
    __shared__ float S [32 * 36];   // scores / probs [q][l]
    __shared__ float mrow[32], lrow[32], srow[32];

    float* Kst = KH;                 // [d*33 + l]
    float* Hs  = KH + 64 * 33;       // [l*64 + d] (16B aligned: 2112 floats = 8448 B)

    const int blk = blockIdx.x;
    const int b = blk >> 8;          // / (NH*W)
    const int h = (blk >> 5) & 7;
    const int i = blk & 31;
    const int tid = threadIdx.x;

    // ---- Phase 1: load Q tile + embeddings, compute bias tables ----
    const float* Qg = g_Q + ((size_t)(b * POSn + i * 32) * OCn) + h * Cn;
    for (int idx = tid; idx < 32 * 64; idx += 256) {
        int q = idx >> 6, d = idx & 63;
        Qs[q * 65 + d] = Qg[(size_t)q * OCn + d];
    }
    float* Remb = KH;                // [k*33 + d], k=0..31 -> row_emb[31-i+k]
    float* Cemb = KH + 32 * 33;      // [r*33 + d], r=0..62 (full col_emb)
    for (int idx = tid; idx < 32 * 32; idx += 256) {
        int k = idx >> 5, d = idx & 31;
        Remb[k * 33 + d] = row_emb[(size_t)(CENTER - i + k) * 32 + d];
    }
    for (int idx = tid; idx < 63 * 32; idx += 256) {
        int r = idx >> 5, d = idx & 31;
        Cemb[r * 33 + d] = col_emb[idx];
    }
    if (tid < 32) { mrow[tid] = -1e30f; lrow[tid] = 0.0f; srow[tid] = 1.0f; }
    __syncthreads();

    for (int e = tid; e < 1024; e += 256) {
        int q = e >> 5, k = e & 31;       // k doubles as l for CB
        float s1 = 0.f, s2 = 0.f;
#pragma unroll
        for (int d = 0; d < 32; d++) {
            s1 += Qs[q * 65 + d]      * Remb[k * 33 + d];
            s2 += Qs[q * 65 + 32 + d] * Cemb[(CENTER - q + k) * 33 + d];
        }
        RB[q * 33 + k] = s1;
        CB[q * 33 + k] = s2;
    }
    __syncthreads();   // phase-1 buffers (Remb/Cemb) now dead; KH becomes Kst/Hs

    // ---- Phase 2: main loop over 32 key-row tiles ----
    float acc[8] = {};
    const int myq = tid >> 3;        // 0..31
    const int dg  = tid & 7;         // 0..7, owns d = dg*8 .. dg*8+7
    const int qh  = tid >> 4;        // 0..15 -> q in {qh, qh+16}
    const int lh  = tid & 15;        // 0..15 -> l in {lh, lh+16}

    const float* Kg = g_K + (size_t)b * POSn * OCn + h * Cn;
    const float* Hg = hs  + (size_t)b * POSn * Cn;

    for (int kr = 0; kr < 32; kr++) {
        // load K tile (transposed) and hidden tile
        for (int idx = tid; idx < 32 * 64; idx += 256) {
            int l = idx >> 6, d = idx & 63;
            Kst[d * 33 + l] = Kg[(size_t)(kr * 32 + l) * OCn + d];
            Hs[idx]         = Hg[(size_t)kr * 2048 + idx];
        }
        __syncthreads();

        // scores: 2q x 2l register tile per thread
        float s00 = 0.f, s01 = 0.f, s10 = 0.f, s11 = 0.f;
#pragma unroll
        for (int d = 0; d < 64; d++) {
            float k0 = Kst[d * 33 + lh];
            float k1 = Kst[d * 33 + lh + 16];
            float q0 = Qs[qh * 65 + d];
            float q1 = Qs[(qh + 16) * 65 + d];
            s00 += q0 * k0; s01 += q0 * k1;
            s10 += q1 * k0; s11 += q1 * k1;
        }
        {
            float rb0 = RB[qh * 33 + kr], rb1 = RB[(qh + 16) * 33 + kr];
            S[qh * 36 + lh]             = (s00 + rb0 + CB[qh * 33 + lh])        * 0.125f;
            S[qh * 36 + lh + 16]        = (s01 + rb0 + CB[qh * 33 + lh + 16])   * 0.125f;
            S[(qh + 16) * 36 + lh]      = (s10 + rb1 + CB[(qh + 16) * 33 + lh]) * 0.125f;
            S[(qh + 16) * 36 + lh + 16] = (s11 + rb1 + CB[(qh + 16) * 33 + lh + 16]) * 0.125f;
        }
        __syncthreads();

        // online softmax update: 8-lane group per query
        {
            const int q = myq, sub = dg;
            float v0 = S[q * 36 + sub * 4 + 0];
            float v1 = S[q * 36 + sub * 4 + 1];
            float v2 = S[q * 36 + sub * 4 + 2];
            float v3 = S[q * 36 + sub * 4 + 3];
            float tmax = fmaxf(fmaxf(v0, v1), fmaxf(v2, v3));
            tmax = fmaxf(tmax, __shfl_xor_sync(0xffffffffu, tmax, 1));
            tmax = fmaxf(tmax, __shfl_xor_sync(0xffffffffu, tmax, 2));
            tmax = fmaxf(tmax, __shfl_xor_sync(0xffffffffu, tmax, 4));
            float m_old = mrow[q];
            float m_new = fmaxf(m_old, tmax);
            float e0 = __expf(v0 - m_new);
            float e1 = __expf(v1 - m_new);
            float e2 = __expf(v2 - m_new);
            float e3 = __expf(v3 - m_new);
            S[q * 36 + sub * 4 + 0] = e0;
            S[q * 36 + sub * 4 + 1] = e1;
            S[q * 36 + sub * 4 + 2] = e2;
            S[q * 36 + sub * 4 + 3] = e3;
            float tsum = e0 + e1 + e2 + e3;
            tsum += __shfl_xor_sync(0xffffffffu, tsum, 1);
            tsum += __shfl_xor_sync(0xffffffffu, tsum, 2);
            tsum += __shfl_xor_sync(0xffffffffu, tsum, 4);
            float sc = __expf(m_old - m_new);
            if (sub == 0) {
                mrow[q] = m_new;
                lrow[q] = lrow[q] * sc + tsum;
                srow[q] = sc;
            }
        }
        __syncthreads();

        // P @ hidden accumulation
        {
            float sc = srow[myq];
#pragma unroll
            for (int u = 0; u < 8; u++) acc[u] *= sc;
            const float4* H4 = reinterpret_cast<const float4*>(Hs);
#pragma unroll
            for (int l = 0; l < 32; l++) {
                float p = S[myq * 36 + l];
                float4 h0 = H4[l * 16 + dg * 2];
                float4 h1 = H4[l * 16 + dg * 2 + 1];
                acc[0] += p * h0.x; acc[1] += p * h0.y;
                acc[2] += p * h0.z; acc[3] += p * h0.w;
                acc[4] += p * h1.x; acc[5] += p * h1.y;
                acc[6] += p * h1.z; acc[7] += p * h1.w;
            }
        }
        __syncthreads();
    }

    // finalize: normalize and write mixed[b, pos, h*64 + d]
    {
        float inv = 1.0f / lrow[myq];
        float* outp = g_mix + ((size_t)(b * POSn + i * 32 + myq) * OCn) + h * Cn + dg * 8;
        float4 o0, o1;
        o0.x = acc[0] * inv; o0.y = acc[1] * inv; o0.z = acc[2] * inv; o0.w = acc[3] * inv;
        o1.x = acc[4] * inv; o1.y = acc[5] * inv; o1.z = acc[6] * inv; o1.w = acc[7] * inv;
        reinterpret_cast<float4*>(outp)[0] = o0;
        reinterpret_cast<float4*>(outp)[1] = o1;
    }
}

// ---------------------------------------------------------------------------
// Kernel C: out = mixed(8192x512) @ Wv^T (64x512) + bv
// grid: 256 (32 rows each)  block: 256
// ---------------------------------------------------------------------------
__global__ __launch_bounds__(256)
void vox_outproj_kernel(const float* __restrict__ Wv,
                        const float* __restrict__ bv,
                        float* __restrict__ out)
{
    __shared__ float Ms[32 * 65];
    __shared__ float Ws[64 * 65];   // [k_local][c]

    const int r0 = blockIdx.x * 32;
    const int tid = threadIdx.x;
    const int ty = tid >> 4;   // 0..15 -> 2 rows
    const int tx = tid & 15;   // 0..15 -> 4 cols

    float acc[2][4] = {};

    for (int k0 = 0; k0 < OCn; k0 += 64) {
        for (int idx = tid; idx < 32 * 64; idx += 256) {
            int r = idx >> 6, c = idx & 63;
            Ms[r * 65 + c] = g_mix[(size_t)(r0 + r) * OCn + k0 + c];
        }
        for (int idx = tid; idx < 64 * 64; idx += 256) {
            int c = idx >> 6, kl = idx & 63;
            Ws[kl * 65 + c] = Wv[(size_t)c * OCn + k0 + kl];
        }
        __syncthreads();
#pragma unroll
        for (int k = 0; k < 64; k++) {
            float a0 = Ms[(ty * 2 + 0) * 65 + k];
            float a1 = Ms[(ty * 2 + 1) * 65 + k];
            float w0 = Ws[k * 65 + tx * 4 + 0];
            float w1 = Ws[k * 65 + tx * 4 + 1];
            float w2 = Ws[k * 65 + tx * 4 + 2];
            float w3 = Ws[k * 65 + tx * 4 + 3];
            acc[0][0] += a0 * w0; acc[0][1] += a0 * w1; acc[0][2] += a0 * w2; acc[0][3] += a0 * w3;
            acc[1][0] += a1 * w0; acc[1][1] += a1 * w1; acc[1][2] += a1 * w2; acc[1][3] += a1 * w3;
        }
        __syncthreads();
    }

#pragma unroll
    for (int u = 0; u < 2; u++) {
        float4 o;
        o.x = acc[u][0] + bv[tx * 4 + 0];
        o.y = acc[u][1] + bv[tx * 4 + 1];
        o.z = acc[u][2] + bv[tx * 4 + 2];
        o.w = acc[u][3] + bv[tx * 4 + 3];
        *reinterpret_cast<float4*>(&out[(size_t)(r0 + ty * 2 + u) * Cn + tx * 4]) = o;
    }
}

// ---------------------------------------------------------------------------
extern "C" void kernel_launch(void* const* d_in, const int* in_sizes, int n_in,
                              void* d_out, int out_size)
{
    const float* hs      = (const float*)d_in[0];
    const float* row_emb = (const float*)d_in[1];
    const float* col_emb = (const float*)d_in[2];
    const float* Wq      = (const float*)d_in[3];
    const float* bq      = (const float*)d_in[4];
    const float* Wk      = (const float*)d_in[5];
    const float* bk      = (const float*)d_in[6];
    const float* Wv      = (const float*)d_in[7];
    const float* bv      = (const float*)d_in[8];
    float* out = (float*)d_out;

    dim3 gA(Bn * POSn / 64, OCn / 64, 2);          // 128 x 8 x 2
    vox_proj_kernel<<<gA, 256>>>(hs, Wq, bq, Wk, bk);

    vox_attn_kernel<<<Bn * NHn * Wn, 256>>>(hs, row_emb, col_emb);   // 2048 blocks

    vox_outproj_kernel<<<Bn * POSn / 32, 256>>>(Wv, bv, out);        // 256 blocks
}

// round 14
// speedup vs baseline: 1.0003x; 1.0003x over previous
#include <cuda_runtime.h>
#include <math.h>

// Problem constants
#define Bn 8
#define Wn 32
#define Hn 32
#define Cn 64
#define NHn 8
#define POSn 1024          // W*H
#define OCn 512            // NH*C
#define CENTER 31

// Device scratch (allocation-free rule: static __device__ globals)
__device__ float g_Q[Bn * POSn * OCn];     // 16 MB
__device__ float g_K[Bn * POSn * OCn];     // 16 MB
__device__ float g_mix[Bn * POSn * OCn];   // 16 MB

// ---------------------------------------------------------------------------
// Kernel A: Q/K projections.  out[pos, o] = sum_c hs[pos,c]*W[o,c] + b[o]
// grid: (8192/64, 512/64, 2)   block: 256
// ---------------------------------------------------------------------------
__global__ __launch_bounds__(256)
void vox_proj_kernel(const float* __restrict__ hs,
                     const float* __restrict__ Wq, const float* __restrict__ bq,
                     const float* __restrict__ Wk, const float* __restrict__ bk)
{
    const float* Wm = blockIdx.z ? Wk : Wq;
    const float* bm = blockIdx.z ? bk : bq;
    float* outp = blockIdx.z ? g_K : g_Q;

    __shared__ float As[64 * 65];
    __shared__ float Ws[64 * 65];

    const int r0 = blockIdx.x * 64;
    const int c0 = blockIdx.y * 64;
    const int tid = threadIdx.x;

    for (int idx = tid; idx < 64 * 64; idx += 256) {
        int r = idx >> 6, c = idx & 63;
        As[r * 65 + c] = hs[(size_t)(r0 + r) * 64 + c];
        Ws[r * 65 + c] = Wm[(size_t)(c0 + r) * 64 + c];   // Ws[o_local][k]
    }
    __syncthreads();

    const int ty = tid >> 4;   // 0..15 -> 4 rows each
    const int tx = tid & 15;   // 0..15 -> 4 cols each

    float acc[4][4] = {};
#pragma unroll
    for (int k = 0; k < 64; k++) {
        float a[4], w[4];
#pragma unroll
        for (int u = 0; u < 4; u++) a[u] = As[(ty * 4 + u) * 65 + k];
#pragma unroll
        for (int v = 0; v < 4; v++) w[v] = Ws[(tx * 4 + v) * 65 + k];
#pragma unroll
        for (int u = 0; u < 4; u++)
#pragma unroll
            for (int v = 0; v < 4; v++)
                acc[u][v] += a[u] * w[v];
    }

#pragma unroll
    for (int u = 0; u < 4; u++) {
        float4 o;
        o.x = acc[u][0] + bm[c0 + tx * 4 + 0];
        o.y = acc[u][1] + bm[c0 + tx * 4 + 1];
        o.z = acc[u][2] + bm[c0 + tx * 4 + 2];
        o.w = acc[u][3] + bm[c0 + tx * 4 + 3];
        *reinterpret_cast<float4*>(&outp[(size_t)(r0 + ty * 4 + u) * OCn + c0 + tx * 4]) = o;
    }
}

// ---------------------------------------------------------------------------
// Kernel B: fused relative-bias attention (flash-style, online softmax).
// One block per (b, h, i) : 32 queries (j=0..31) x 1024 keys.
// grid: 2048   block: 256
// ---------------------------------------------------------------------------
__global__ __launch_bounds__(256)
void vox_attn_kernel(const float* __restrict__ hs,
                     const float* __restrict__ row_emb,
                     const float* __restrict__ col_emb)
{
    __shared__ __align__(16) float KH[64 * 33 + 32 * 64]; // Kst(2112f) + Hs(2048f); phase1: Remb+Cemb alias
    __shared__ float Qs[32 * 65];   // [q][d], pad 65
    __shared__ float RB[32 * 33];   // rb[q][k]
    __shared__ float CB[32 * 33];   // cb[q][l]
    __shared__ float S [32 * 36];   // scores / probs [q][l]
    __shared__ float mrow[32], lrow[32], srow[32];

    float* Kst = KH;                 // [d*33 + l]
    float* Hs  = KH + 64 * 33;       // [l*64 + d] (16B aligned: 2112 floats = 8448 B)

    const int blk = blockIdx.x;
    const int b = blk >> 8;          // / (NH*W)
    const int h = (blk >> 5) & 7;
    const int i = blk & 31;
    const int tid = threadIdx.x;

    // ---- Phase 1: load Q tile + embeddings, compute bias tables ----
    const float* Qg = g_Q + ((size_t)(b * POSn + i * 32) * OCn) + h * Cn;
    for (int idx = tid; idx < 32 * 64; idx += 256) {
        int q = idx >> 6, d = idx & 63;
        Qs[q * 65 + d] = Qg[(size_t)q * OCn + d];
    }
    float* Remb = KH;                // [k*33 + d], k=0..31 -> row_emb[31-i+k]
    float* Cemb = KH + 32 * 33;      // [r*33 + d], r=0..62 (full col_emb)
    for (int idx = tid; idx < 32 * 32; idx += 256) {
        int k = idx >> 5, d = idx & 31;
        Remb[k * 33 + d] = row_emb[(size_t)(CENTER - i + k) * 32 + d];
    }
    for (int idx = tid; idx < 63 * 32; idx += 256) {
        int r = idx >> 5, d = idx & 31;
        Cemb[r * 33 + d] = col_emb[idx];
    }
    if (tid < 32) { mrow[tid] = -1e30f; lrow[tid] = 0.0f; srow[tid] = 1.0f; }
    __syncthreads();

    for (int e = tid; e < 1024; e += 256) {
        int q = e >> 5, k = e & 31;       // k doubles as l for CB
        float s1 = 0.f, s2 = 0.f;
#pragma unroll
        for (int d = 0; d < 32; d++) {
            s1 += Qs[q * 65 + d]      * Remb[k * 33 + d];
            s2 += Qs[q * 65 + 32 + d] * Cemb[(CENTER - q + k) * 33 + d];
        }
        RB[q * 33 + k] = s1;
        CB[q * 33 + k] = s2;
    }
    __syncthreads();   // phase-1 buffers (Remb/Cemb) now dead; KH becomes Kst/Hs

    // ---- Phase 2: main loop over 32 key-row tiles ----
    float acc[8] = {};
    const int myq = tid >> 3;        // 0..31
    const int dg  = tid & 7;         // 0..7, owns d = dg*8 .. dg*8+7
    const int qh  = tid >> 4;        // 0..15 -> q in {qh, qh+16}
    const int lh  = tid & 15;        // 0..15 -> l in {lh, lh+16}

    const float* Kg = g_K + (size_t)b * POSn * OCn + h * Cn;
    const float* Hg = hs  + (size_t)b * POSn * Cn;

    for (int kr = 0; kr < 32; kr++) {
        // load K tile (transposed) and hidden tile
        for (int idx = tid; idx < 32 * 64; idx += 256) {
            int l = idx >> 6, d = idx & 63;
            Kst[d * 33 + l] = Kg[(size_t)(kr * 32 + l) * OCn + d];
            Hs[idx]         = Hg[(size_t)kr * 2048 + idx];
        }
        __syncthreads();

        // scores: 2q x 2l register tile per thread
        float s00 = 0.f, s01 = 0.f, s10 = 0.f, s11 = 0.f;
#pragma unroll
        for (int d = 0; d < 64; d++) {
            float k0 = Kst[d * 33 + lh];
            float k1 = Kst[d * 33 + lh + 16];
            float q0 = Qs[qh * 65 + d];
            float q1 = Qs[(qh + 16) * 65 + d];
            s00 += q0 * k0; s01 += q0 * k1;
            s10 += q1 * k0; s11 += q1 * k1;
        }
        {
            float rb0 = RB[qh * 33 + kr], rb1 = RB[(qh + 16) * 33 + kr];
            S[qh * 36 + lh]             = (s00 + rb0 + CB[qh * 33 + lh])        * 0.125f;
            S[qh * 36 + lh + 16]        = (s01 + rb0 + CB[qh * 33 + lh + 16])   * 0.125f;
            S[(qh + 16) * 36 + lh]      = (s10 + rb1 + CB[(qh + 16) * 33 + lh]) * 0.125f;
            S[(qh + 16) * 36 + lh + 16] = (s11 + rb1 + CB[(qh + 16) * 33 + lh + 16]) * 0.125f;
        }
        __syncthreads();

        // online softmax update: 8-lane group per query
        {
            const int q = myq, sub = dg;
            float v0 = S[q * 36 + sub * 4 + 0];
            float v1 = S[q * 36 + sub * 4 + 1];
            float v2 = S[q * 36 + sub * 4 + 2];
            float v3 = S[q * 36 + sub * 4 + 3];
            float tmax = fmaxf(fmaxf(v0, v1), fmaxf(v2, v3));
            tmax = fmaxf(tmax, __shfl_xor_sync(0xffffffffu, tmax, 1));
            tmax = fmaxf(tmax, __shfl_xor_sync(0xffffffffu, tmax, 2));
            tmax = fmaxf(tmax, __shfl_xor_sync(0xffffffffu, tmax, 4));
            float m_old = mrow[q];
            float m_new = fmaxf(m_old, tmax);
            float e0 = __expf(v0 - m_new);
            float e1 = __expf(v1 - m_new);
            float e2 = __expf(v2 - m_new);
            float e3 = __expf(v3 - m_new);
            S[q * 36 + sub * 4 + 0] = e0;
            S[q * 36 + sub * 4 + 1] = e1;
            S[q * 36 + sub * 4 + 2] = e2;
            S[q * 36 + sub * 4 + 3] = e3;
            float tsum = e0 + e1 + e2 + e3;
            tsum += __shfl_xor_sync(0xffffffffu, tsum, 1);
            tsum += __shfl_xor_sync(0xffffffffu, tsum, 2);
            tsum += __shfl_xor_sync(0xffffffffu, tsum, 4);
            float sc = __expf(m_old - m_new);
            if (sub == 0) {
                mrow[q] = m_new;
                lrow[q] = lrow[q] * sc + tsum;
                srow[q] = sc;
            }
        }
        __syncthreads();

        // P @ hidden accumulation
        {
            float sc = srow[myq];
#pragma unroll
            for (int u = 0; u < 8; u++) acc[u] *= sc;
            const float4* H4 = reinterpret_cast<const float4*>(Hs);
#pragma unroll
            for (int l = 0; l < 32; l++) {
                float p = S[myq * 36 + l];
                float4 h0 = H4[l * 16 + dg * 2];
                float4 h1 = H4[l * 16 + dg * 2 + 1];
                acc[0] += p * h0.x; acc[1] += p * h0.y;
                acc[2] += p * h0.z; acc[3] += p * h0.w;
                acc[4] += p * h1.x; acc[5] += p * h1.y;
                acc[6] += p * h1.z; acc[7] += p * h1.w;
            }
        }
        __syncthreads();
    }

    // finalize: normalize and write mixed[b, pos, h*64 + d]
    {
        float inv = 1.0f / lrow[myq];
        float* outp = g_mix + ((size_t)(b * POSn + i * 32 + myq) * OCn) + h * Cn + dg * 8;
        float4 o0, o1;
        o0.x = acc[0] * inv; o0.y = acc[1] * inv; o0.z = acc[2] * inv; o0.w = acc[3] * inv;
        o1.x = acc[4] * inv; o1.y = acc[5] * inv; o1.z = acc[6] * inv; o1.w = acc[7] * inv;
        reinterpret_cast<float4*>(outp)[0] = o0;
        reinterpret_cast<float4*>(outp)[1] = o1;
    }
}

// ---------------------------------------------------------------------------
// Kernel C: out = mixed(8192x512) @ Wv^T (64x512) + bv
// grid: 256 (32 rows each)  block: 256
// ---------------------------------------------------------------------------
__global__ __launch_bounds__(256)
void vox_outproj_kernel(const float* __restrict__ Wv,
                        const float* __restrict__ bv,
                        float* __restrict__ out)
{
    __shared__ float Ms[32 * 65];
    __shared__ float Ws[64 * 65];   // [k_local][c]

    const int r0 = blockIdx.x * 32;
    const int tid = threadIdx.x;
    const int ty = tid >> 4;   // 0..15 -> 2 rows
    const int tx = tid & 15;   // 0..15 -> 4 cols

    float acc[2][4] = {};

    for (int k0 = 0; k0 < OCn; k0 += 64) {
        for (int idx = tid; idx < 32 * 64; idx += 256) {
            int r = idx >> 6, c = idx & 63;
            Ms[r * 65 + c] = g_mix[(size_t)(r0 + r) * OCn + k0 + c];
        }
        for (int idx = tid; idx < 64 * 64; idx += 256) {
            int c = idx >> 6, kl = idx & 63;
            Ws[kl * 65 + c] = Wv[(size_t)c * OCn + k0 + kl];
        }
        __syncthreads();
#pragma unroll
        for (int k = 0; k < 64; k++) {
            float a0 = Ms[(ty * 2 + 0) * 65 + k];
            float a1 = Ms[(ty * 2 + 1) * 65 + k];
            float w0 = Ws[k * 65 + tx * 4 + 0];
            float w1 = Ws[k * 65 + tx * 4 + 1];
            float w2 = Ws[k * 65 + tx * 4 + 2];
            float w3 = Ws[k * 65 + tx * 4 + 3];
            acc[0][0] += a0 * w0; acc[0][1] += a0 * w1; acc[0][2] += a0 * w2; acc[0][3] += a0 * w3;
            acc[1][0] += a1 * w0; acc[1][1] += a1 * w1; acc[1][2] += a1 * w2; acc[1][3] += a1 * w3;
        }
        __syncthreads();
    }

#pragma unroll
    for (int u = 0; u < 2; u++) {
        float4 o;
        o.x = acc[u][0] + bv[tx * 4 + 0];
        o.y = acc[u][1] + bv[tx * 4 + 1];
        o.z = acc[u][2] + bv[tx * 4 + 2];
        o.w = acc[u][3] + bv[tx * 4 + 3];
        *reinterpret_cast<float4*>(&out[(size_t)(r0 + ty * 2 + u) * Cn + tx * 4]) = o;
    }
}

// ---------------------------------------------------------------------------
extern "C" void kernel_launch(void* const* d_in, const int* in_sizes, int n_in,
                              void* d_out, int out_size)
{
    const float* hs      = (const float*)d_in[0];
    const float* row_emb = (const float*)d_in[1];
    const float* col_emb = (const float*)d_in[2];
    const float* Wq      = (const float*)d_in[3];
    const float* bq      = (const float*)d_in[4];
    const float* Wk      = (const float*)d_in[5];
    const float* bk      = (const float*)d_in[6];
    const float* Wv      = (const float*)d_in[7];
    const float* bv      = (const float*)d_in[8];
    float* out = (float*)d_out;

    dim3 gA(Bn * POSn / 64, OCn / 64, 2);          // 128 x 8 x 2
    vox_proj_kernel<<<gA, 256>>>(hs, Wq, bq, Wk, bk);

    vox_attn_kernel<<<Bn * NHn * Wn, 256>>>(hs, row_emb, col_emb);   // 2048 blocks

    vox_outproj_kernel<<<Bn * POSn / 32, 256>>>(Wv, bv, out);        // 256 blocks
}

// round 17
// speedup vs baseline: 1.0005x; 1.0003x over previous
#include <cuda_runtime.h>
#include <math.h>

// Problem constants
#define Bn 8
#define Wn 32
#define Hn 32
#define Cn 64
#define NHn 8
#define POSn 1024          // W*H
#define OCn 512            // NH*C
#define CENTER 31

// Device scratch (allocation-free rule: static __device__ globals)
__device__ float g_Q[Bn * POSn * OCn];     // 16 MB
__device__ float g_K[Bn * POSn * OCn];     // 16 MB
__device__ float g_mix[Bn * POSn * OCn];   // 16 MB

// ---------------------------------------------------------------------------
// Kernel A: Q/K projections.  out[pos, o] = sum_c hs[pos,c]*W[o,c] + b[o]
// grid: (8192/64, 512/64, 2)   block: 256
// ---------------------------------------------------------------------------
__global__ __launch_bounds__(256)
void vox_proj_kernel(const float* __restrict__ hs,
                     const float* __restrict__ Wq, const float* __restrict__ bq,
                     const float* __restrict__ Wk, const float* __restrict__ bk)
{
    const float* Wm = blockIdx.z ? Wk : Wq;
    const float* bm = blockIdx.z ? bk : bq;
    float* outp = blockIdx.z ? g_K : g_Q;

    __shared__ float As[64 * 65];
    __shared__ float Ws[64 * 65];

    const int r0 = blockIdx.x * 64;
    const int c0 = blockIdx.y * 64;
    const int tid = threadIdx.x;

    for (int idx = tid; idx < 64 * 64; idx += 256) {
        int r = idx >> 6, c = idx & 63;
        As[r * 65 + c] = hs[(size_t)(r0 + r) * 64 + c];
        Ws[r * 65 + c] = Wm[(size_t)(c0 + r) * 64 + c];   // Ws[o_local][k]
    }
    __syncthreads();

    const int ty = tid >> 4;   // 0..15 -> 4 rows each
    const int tx = tid & 15;   // 0..15 -> 4 cols each

    float acc[4][4] = {};
#pragma unroll
    for (int k = 0; k < 64; k++) {
        float a[4], w[4];
#pragma unroll
        for (int u = 0; u < 4; u++) a[u] = As[(ty * 4 + u) * 65 + k];
#pragma unroll
        for (int v = 0; v < 4; v++) w[v] = Ws[(tx * 4 + v) * 65 + k];
#pragma unroll
        for (int u = 0; u < 4; u++)
#pragma unroll
            for (int v = 0; v < 4; v++)
                acc[u][v] += a[u] * w[v];
    }

#pragma unroll
    for (int u = 0; u < 4; u++) {
        float4 o;
        o.x = acc[u][0] + bm[c0 + tx * 4 + 0];
        o.y = acc[u][1] + bm[c0 + tx * 4 + 1];
        o.z = acc[u][2] + bm[c0 + tx * 4 + 2];
        o.w = acc[u][3] + bm[c0 + tx * 4 + 3];
        *reinterpret_cast<float4*>(&outp[(size_t)(r0 + ty * 4 + u) * OCn + c0 + tx * 4]) = o;
    }
}

// ---------------------------------------------------------------------------
// Kernel B: fused relative-bias attention (flash-style, online softmax).
// One block per (b, h, i) : 32 queries (j=0..31) x 1024 keys.
// grid: 2048   block: 256
// ---------------------------------------------------------------------------
__global__ __launch_bounds__(256)
void vox_attn_kernel(const float* __restrict__ hs,
                     const float* __restrict__ row_emb,
                     const float* __restrict__ col_emb)
{
    __shared__ __align__(16) float KH[64 * 33 + 32 * 64]; // Kst(2112f) + Hs(2048f); phase1: Remb+Cemb alias
    __shared__ float Qs[32 * 65];   // [q][d], pad 65
    __shared__ float RB[32 * 33];   // rb[q][k]
    __shared__ float CB[32 * 33];   // cb[q][l]
    __shared__ float S [32 * 36];   // scores / probs [q][l]
    __shared__ float mrow[32], lrow[32], srow[32];

    float* Kst = KH;                 // [d*33 + l]
    float* Hs  = KH + 64 * 33;       // [l*64 + d] (16B aligned: 2112 floats = 8448 B)

    const int blk = blockIdx.x;
    const int b = blk >> 8;          // / (NH*W)
    const int h = (blk >> 5) & 7;
    const int i = blk & 31;
    const int tid = threadIdx.x;

    // ---- Phase 1: load Q tile + embeddings, compute bias tables ----
    const float* Qg = g_Q + ((size_t)(b * POSn + i * 32) * OCn) + h * Cn;
    for (int idx = tid; idx < 32 * 64; idx += 256) {
        int q = idx >> 6, d = idx & 63;
        Qs[q * 65 + d] = Qg[(size_t)q * OCn + d];
    }
    float* Remb = KH;                // [k*33 + d], k=0..31 -> row_emb[31-i+k]
    float* Cemb = KH + 32 * 33;      // [r*33 + d], r=0..62 (full col_emb)
    for (int idx = tid; idx < 32 * 32; idx += 256) {
        int k = idx >> 5, d = idx & 31;
        Remb[k * 33 + d] = row_emb[(size_t)(CENTER - i + k) * 32 + d];
    }
    for (int idx = tid; idx < 63 * 32; idx += 256) {
        int r = idx >> 5, d = idx & 31;
        Cemb[r * 33 + d] = col_emb[idx];
    }
    if (tid < 32) { mrow[tid] = -1e30f; lrow[tid] = 0.0f; srow[tid] = 1.0f; }
    __syncthreads();

    for (int e = tid; e < 1024; e += 256) {
        int q = e >> 5, k = e & 31;       // k doubles as l for CB
        float s1 = 0.f, s2 = 0.f;
#pragma unroll
        for (int d = 0; d < 32; d++) {
            s1 += Qs[q * 65 + d]      * Remb[k * 33 + d];
            s2 += Qs[q * 65 + 32 + d] * Cemb[(CENTER - q + k) * 33 + d];
        }
        RB[q * 33 + k] = s1;
        CB[q * 33 + k] = s2;
    }
    __syncthreads();   // phase-1 buffers (Remb/Cemb) now dead; KH becomes Kst/Hs

    // ---- Phase 2: main loop over 32 key-row tiles ----
    float acc[8] = {};
    const int myq = tid >> 3;        // 0..31
    const int dg  = tid & 7;         // 0..7, owns d = dg*8 .. dg*8+7
    const int qh  = tid >> 4;        // 0..15 -> q in {qh, qh+16}
    const int lh  = tid & 15;        // 0..15 -> l in {lh, lh+16}

    const float* Kg = g_K + (size_t)b * POSn * OCn + h * Cn;
    const float* Hg = hs  + (size_t)b * POSn * Cn;

    for (int kr = 0; kr < 32; kr++) {
        // load K tile (transposed) and hidden tile
        for (int idx = tid; idx < 32 * 64; idx += 256) {
            int l = idx >> 6, d = idx & 63;
            Kst[d * 33 + l] = Kg[(size_t)(kr * 32 + l) * OCn + d];
            Hs[idx]         = Hg[(size_t)kr * 2048 + idx];
        }
        __syncthreads();

        // scores: 2q x 2l register tile per thread
        float s00 = 0.f, s01 = 0.f, s10 = 0.f, s11 = 0.f;
#pragma unroll
        for (int d = 0; d < 64; d++) {
            float k0 = Kst[d * 33 + lh];
            float k1 = Kst[d * 33 + lh + 16];
            float q0 = Qs[qh * 65 + d];
            float q1 = Qs[(qh + 16) * 65 + d];
            s00 += q0 * k0; s01 += q0 * k1;
            s10 += q1 * k0; s11 += q1 * k1;
        }
        {
            float rb0 = RB[qh * 33 + kr], rb1 = RB[(qh + 16) * 33 + kr];
            S[qh * 36 + lh]             = (s00 + rb0 + CB[qh * 33 + lh])        * 0.125f;
            S[qh * 36 + lh + 16]        = (s01 + rb0 + CB[qh * 33 + lh + 16])   * 0.125f;
            S[(qh + 16) * 36 + lh]      = (s10 + rb1 + CB[(qh + 16) * 33 + lh]) * 0.125f;
            S[(qh + 16) * 36 + lh + 16] = (s11 + rb1 + CB[(qh + 16) * 33 + lh + 16]) * 0.125f;
        }
        __syncthreads();

        // online softmax update: 8-lane group per query
        {
            const int q = myq, sub = dg;
            float v0 = S[q * 36 + sub * 4 + 0];
            float v1 = S[q * 36 + sub * 4 + 1];
            float v2 = S[q * 36 + sub * 4 + 2];
            float v3 = S[q * 36 + sub * 4 + 3];
            float tmax = fmaxf(fmaxf(v0, v1), fmaxf(v2, v3));
            tmax = fmaxf(tmax, __shfl_xor_sync(0xffffffffu, tmax, 1));
            tmax = fmaxf(tmax, __shfl_xor_sync(0xffffffffu, tmax, 2));
            tmax = fmaxf(tmax, __shfl_xor_sync(0xffffffffu, tmax, 4));
            float m_old = mrow[q];
            float m_new = fmaxf(m_old, tmax);
            float e0 = __expf(v0 - m_new);
            float e1 = __expf(v1 - m_new);
            float e2 = __expf(v2 - m_new);
            float e3 = __expf(v3 - m_new);
            S[q * 36 + sub * 4 + 0] = e0;
            S[q * 36 + sub * 4 + 1] = e1;
            S[q * 36 + sub * 4 + 2] = e2;
            S[q * 36 + sub * 4 + 3] = e3;
            float tsum = e0 + e1 + e2 + e3;
            tsum += __shfl_xor_sync(0xffffffffu, tsum, 1);
            tsum += __shfl_xor_sync(0xffffffffu, tsum, 2);
            tsum += __shfl_xor_sync(0xffffffffu, tsum, 4);
            float sc = __expf(m_old - m_new);
            if (sub == 0) {
                mrow[q] = m_new;
                lrow[q] = lrow[q] * sc + tsum;
                srow[q] = sc;
            }
        }
        __syncthreads();

        // P @ hidden accumulation
        {
            float sc = srow[myq];
#pragma unroll
            for (int u = 0; u < 8; u++) acc[u] *= sc;
            const float4* H4 = reinterpret_cast<const float4*>(Hs);
#pragma unroll
            for (int l = 0; l < 32; l++) {
                float p = S[myq * 36 + l];
                float4 h0 = H4[l * 16 + dg * 2];
                float4 h1 = H4[l * 16 + dg * 2 + 1];
                acc[0] += p * h0.x; acc[1] += p * h0.y;
                acc[2] += p * h0.z; acc[3] += p * h0.w;
                acc[4] += p * h1.x; acc[5] += p * h1.y;
                acc[6] += p * h1.z; acc[7] += p * h1.w;
            }
        }
        __syncthreads();
    }

    // finalize: normalize and write mixed[b, pos, h*64 + d]
    {
        float inv = 1.0f / lrow[myq];
        float* outp = g_mix + ((size_t)(b * POSn + i * 32 + myq) * OCn) + h * Cn + dg * 8;
        float4 o0, o1;
        o0.x = acc[0] * inv; o0.y = acc[1] * inv; o0.z = acc[2] * inv; o0.w = acc[3] * inv;
        o1.x = acc[4] * inv; o1.y = acc[5] * inv; o1.z = acc[6] * inv; o1.w = acc[7] * inv;
        reinterpret_cast<float4*>(outp)[0] = o0;
        reinterpret_cast<float4*>(outp)[1] = o1;
    }
}

// ---------------------------------------------------------------------------
// Kernel C: out = mixed(8192x512) @ Wv^T (64x512) + bv
// grid: 256 (32 rows each)  block: 256
// ---------------------------------------------------------------------------
__global__ __launch_bounds__(256)
void vox_outproj_kernel(const float* __restrict__ Wv,
                        const float* __restrict__ bv,
                        float* __restrict__ out)
{
    __shared__ float Ms[32 * 65];
    __shared__ float Ws[64 * 65];   // [k_local][c]

    const int r0 = blockIdx.x * 32;
    const int tid = threadIdx.x;
    const int ty = tid >> 4;   // 0..15 -> 2 rows
    const int tx = tid & 15;   // 0..15 -> 4 cols

    float acc[2][4] = {};

    for (int k0 = 0; k0 < OCn; k0 += 64) {
        for (int idx = tid; idx < 32 * 64; idx += 256) {
            int r = idx >> 6, c = idx & 63;
            Ms[r * 65 + c] = g_mix[(size_t)(r0 + r) * OCn + k0 + c];
        }
        for (int idx = tid; idx < 64 * 64; idx += 256) {
            int c = idx >> 6, kl = idx & 63;
            Ws[kl * 65 + c] = Wv[(size_t)c * OCn + k0 + kl];
        }
        __syncthreads();
#pragma unroll
        for (int k = 0; k < 64; k++) {
            float a0 = Ms[(ty * 2 + 0) * 65 + k];
            float a1 = Ms[(ty * 2 + 1) * 65 + k];
            float w0 = Ws[k * 65 + tx * 4 + 0];
            float w1 = Ws[k * 65 + tx * 4 + 1];
            float w2 = Ws[k * 65 + tx * 4 + 2];
            float w3 = Ws[k * 65 + tx * 4 + 3];
            acc[0][0] += a0 * w0; acc[0][1] += a0 * w1; acc[0][2] += a0 * w2; acc[0][3] += a0 * w3;
            acc[1][0] += a1 * w0; acc[1][1] += a1 * w1; acc[1][2] += a1 * w2; acc[1][3] += a1 * w3;
        }
        __syncthreads();
    }

#pragma unroll
    for (int u = 0; u < 2; u++) {
        float4 o;
        o.x = acc[u][0] + bv[tx * 4 + 0];
        o.y = acc[u][1] + bv[tx * 4 + 1];
        o.z = acc[u][2] + bv[tx * 4 + 2];
        o.w = acc[u][3] + bv[tx * 4 + 3];
        *reinterpret_cast<float4*>(&out[(size_t)(r0 + ty * 2 + u) * Cn + tx * 4]) = o;
    }
}

// ---------------------------------------------------------------------------
extern "C" void kernel_launch(void* const* d_in, const int* in_sizes, int n_in,
                              void* d_out, int out_size)
{
    const float* hs      = (const float*)d_in[0];
    const float* row_emb = (const float*)d_in[1];
    const float* col_emb = (const float*)d_in[2];
    const float* Wq      = (const float*)d_in[3];
    const float* bq      = (const float*)d_in[4];
    const float* Wk      = (const float*)d_in[5];
    const float* bk      = (const float*)d_in[6];
    const float* Wv      = (const float*)d_in[7];
    const float* bv      = (const float*)d_in[8];
    float* out = (float*)d_out;

    dim3 gA(Bn * POSn / 64, OCn / 64, 2);          // 128 x 8 x 2
    vox_proj_kernel<<<gA, 256>>>(hs, Wq, bq, Wk, bk);

    vox_attn_kernel<<<Bn * NHn * Wn, 256>>>(hs, row_emb, col_emb);   // 2048 blocks

    vox_outproj_kernel<<<Bn * POSn / 32, 256>>>(Wv, bv, out);        // 256 blocks
}